// round 14
// baseline (speedup 1.0000x reference)
#include <cuda_runtime.h>
#include <cuda_fp16.h>
#include <cuda_bf16.h>
#include <math_constants.h>
#include <cstdint>

// ---------------------------------------------------------------- constants
#define NROWS 16384   // B*H*W
#define NE    8192
#define EDIM  256
#define CH    256
#define HWSZ  1024
#define ZQ_ELEMS 4194304
#define LOSS_OFF 4194304
#define IDX_OFF  4194305
#define CAP   64      // shortlist capacity per row

#define SCREEN_SMEM 99840
#define CT_TENSOR 52            // candTiles on the tensor path
#define CT_FFMA   12            // candTiles on the FFMA path
#define FF_CT0    CT_TENSOR

// ---------------------------------------------------------------- scratch
__device__ float    g_zz[NROWS];
__device__ float    g_ee[NE];
__device__ int      g_idx[NROWS];
__device__ double   g_loss;
__device__ unsigned g_maxee;
__device__ unsigned g_rowmin[NROWS];        // order-mapped float
__device__ int      g_ccount[NROWS];
__device__ int      g_clist[NROWS][CAP];
__device__ float    g_Azf[NROWS * EDIM];    // z transposed, fp32
__device__ uint16_t g_Abf[NROWS * EDIM];    // z transposed, bf16
__device__ uint16_t g_Bbf[NE * EDIM];       // codebook, bf16

// ---- second stream + fork/join events, created pre-main (no device mem)
static cudaStream_t g_s2;
static cudaEvent_t  g_ev1, g_ev2;
namespace {
struct StreamInit {
    StreamInit() {
        cudaStreamCreateWithFlags(&g_s2, cudaStreamNonBlocking);
        cudaEventCreateWithFlags(&g_ev1, cudaEventDisableTiming);
        cudaEventCreateWithFlags(&g_ev2, cudaEventDisableTiming);
    }
};
StreamInit g_stream_init;
}

__device__ __forceinline__ unsigned fmap(float f) {
    unsigned u = __float_as_uint(f);
    return (u & 0x80000000u) ? ~u : (u | 0x80000000u);
}
__device__ __forceinline__ float funmap(unsigned u) {
    u = (u & 0x80000000u) ? (u & 0x7FFFFFFFu) : ~u;
    return __uint_as_float(u);
}
__device__ __forceinline__ uint32_t smem_u32(const void* p) {
    uint32_t a;
    asm("{ .reg .u64 t; cvta.to.shared.u64 t, %1; cvt.u32.u64 %0, t; }" : "=r"(a) : "l"(p));
    return a;
}

// ---------------------------------------------------------------------------
__global__ void init_kernel() { g_maxee = 0; g_loss = 0.0; }

// prep: zz (ref rounding: unfused mul+add, ascending), ee (+ maxee),
//       reset rowmin/ccount
__global__ void prep_kernel(const float* __restrict__ z,
                            const float* __restrict__ cb) {
    int t = blockIdx.x * blockDim.x + threadIdx.x;
    if (t < NROWS) {
        g_rowmin[t] = 0xFFFFFFFFu;
        g_ccount[t] = 0;
        int b = t >> 10, hw = t & 1023;
        const float* p = z + (size_t)b * CH * HWSZ + hw;
        float s = 0.0f;
#pragma unroll 8
        for (int c = 0; c < CH; c++) {
            float v = p[c * HWSZ];
            s = __fadd_rn(s, __fmul_rn(v, v));
        }
        g_zz[t] = s;
    } else if (t < NROWS + NE) {
        int k = t - NROWS;
        const float* p = cb + (size_t)k * EDIM;
        float s = 0.0f;
#pragma unroll 8
        for (int d = 0; d < EDIM; d++) {
            float v = p[d];
            s = __fadd_rn(s, __fmul_rn(v, v));
        }
        g_ee[k] = s;
        atomicMax(&g_maxee, __float_as_uint(s));   // s >= 0: uint order ok
    }
}

// codebook -> bf16
__global__ void split_cb_kernel(const float* __restrict__ cb) {
    int i = blockIdx.x * blockDim.x + threadIdx.x;
    if (i < NE * EDIM) {
        __nv_bfloat16 h = __float2bfloat16_rn(cb[i]);
        g_Bbf[i] = *(uint16_t*)&h;
    }
}

// z: NCHW -> row-major [NROWS][EDIM], fp32 + bf16
__global__ void split_z_kernel(const float* __restrict__ z) {
    __shared__ float s[32][33];
    int b = blockIdx.z, c0 = blockIdx.y * 32, hw0 = blockIdx.x * 32;
    int tx = threadIdx.x, ty = threadIdx.y;   // block (32, 8)
    const float* zp = z + ((size_t)b * CH + c0) * HWSZ + hw0;
#pragma unroll
    for (int i = 0; i < 4; i++) {
        int cl = ty + i * 8;
        s[cl][tx] = zp[(size_t)cl * HWSZ + tx];
    }
    __syncthreads();
#pragma unroll
    for (int i = 0; i < 4; i++) {
        int hl = ty + i * 8;
        size_t o = (size_t)(b * HWSZ + hw0 + hl) * EDIM + c0 + tx;
        float x = s[tx][hl];
        g_Azf[o] = x;
        __nv_bfloat16 h = __float2bfloat16_rn(x);
        g_Abf[o] = *(uint16_t*)&h;
    }
}

// ---------------------------------------------------------------------------
// TENSOR screen (R7, proven): bf16 mma.sync + ldmatrix + cp.async, CTA
// 128 rows x 128 cands, K=256 in 4 chunks, candTiles [0, CT_TENSOR).
// thr = gmin + 2*eps_bf16 (0.024 coeff).
// ---------------------------------------------------------------------------
extern __shared__ __align__(16) uint8_t dsmem[];

#define CP_ASYNC(dst, src) \
    asm volatile("cp.async.cg.shared.global [%0], [%1], 16;" :: "r"(dst), "l"(src) : "memory")
#define CP_COMMIT() asm volatile("cp.async.commit_group;" ::: "memory")
#define CP_WAIT(n)  asm volatile("cp.async.wait_group %0;" :: "n"(n) : "memory")
#define LDMX4(r0, r1, r2, r3, addr)                                            \
    asm volatile("ldmatrix.sync.aligned.m8n8.x4.shared.b16 {%0,%1,%2,%3}, [%4];" \
                 : "=r"(r0), "=r"(r1), "=r"(r2), "=r"(r3) : "r"(addr))

__global__ void __launch_bounds__(256, 2) screen_kernel() {
    const int tid = threadIdx.x, lane = tid & 31, wid = tid >> 5;
    const int rowTile  = blockIdx.x & 127;
    const int candTile = blockIdx.x >> 7;
    const int row0 = rowTile * 128, cand0 = candTile * 128;
    const int wm = wid & 3, wn = wid >> 2;
    const int g = lane >> 2, tg = lane & 3;

    uint8_t*  sAp    = dsmem;
    uint8_t*  sBp    = dsmem + 49152;
    unsigned* s_rmin = (unsigned*)(dsmem + 98304);
    float*    s_thr  = (float*)(dsmem + 98816);
    float*    s_ee   = (float*)(dsmem + 99328);
    const uint32_t smA = smem_u32(sAp);
    const uint32_t smB = smem_u32(sBp);

    if (tid < 128) {
        s_rmin[tid] = 0xFFFFFFFFu;
        s_ee[tid]   = g_ee[cand0 + tid];
    }

    const int rl  = lane & 7;
    const int sel = lane >> 3;
    uint32_t aOff[2], aM7[2];
#pragma unroll
    for (int mf = 0; mf < 2; mf++) {
        int row = wm * 32 + mf * 16 + (sel & 1) * 8 + rl;
        aOff[mf] = (uint32_t)(row * 128);
        aM7[mf]  = (uint32_t)(row & 7);
    }
    const uint32_t aCs = (uint32_t)(sel >> 1);
    uint32_t bOff[4], bM7[4];
#pragma unroll
    for (int p = 0; p < 4; p++) {
        int row = wn * 64 + p * 16 + (sel >> 1) * 8 + rl;
        bOff[p] = (uint32_t)(row * 128);
        bM7[p]  = (uint32_t)(row & 7);
    }
    const uint32_t bCs = (uint32_t)(sel & 1);

    float acc[2][8][4];
#pragma unroll
    for (int mf = 0; mf < 2; mf++)
#pragma unroll
        for (int nf = 0; nf < 8; nf++)
#pragma unroll
            for (int q = 0; q < 4; q++) acc[mf][nf][q] = 0.0f;

#define LOAD_CHUNK(stage, kc)                                                  \
    {                                                                          \
        _Pragma("unroll")                                                      \
        for (int it = 0; it < 4; it++) {                                       \
            int u = tid + it * 256;                                            \
            int r = u >> 3, c = u & 7;                                         \
            uint32_t so = (uint32_t)((stage) * 16384 + r * 128 + ((c ^ (r & 7)) << 4)); \
            CP_ASYNC(smA + so, g_Abf + (size_t)(row0 + r) * EDIM + (kc) * 64 + c * 8);  \
            CP_ASYNC(smB + so, g_Bbf + (size_t)(cand0 + r) * EDIM + (kc) * 64 + c * 8); \
        }                                                                      \
        CP_COMMIT();                                                           \
    }
#define MMA_CHUNK(stage)                                                       \
    {                                                                          \
        const uint32_t bufA = smA + (stage) * 16384;                           \
        const uint32_t bufB = smB + (stage) * 16384;                           \
        _Pragma("unroll")                                                      \
        for (int ks = 0; ks < 4; ks++) {                                       \
            uint32_t a[2][4], b[8][2];                                         \
            const uint32_t ca  = (uint32_t)(2 * ks) + aCs;                     \
            const uint32_t cbk = (uint32_t)(2 * ks) + bCs;                     \
            _Pragma("unroll")                                                  \
            for (int mf = 0; mf < 2; mf++) {                                   \
                uint32_t addr = bufA + aOff[mf] + (((ca ^ aM7[mf]) & 7u) << 4); \
                LDMX4(a[mf][0], a[mf][1], a[mf][2], a[mf][3], addr);           \
            }                                                                  \
            _Pragma("unroll")                                                  \
            for (int p = 0; p < 4; p++) {                                      \
                uint32_t addr = bufB + bOff[p] + (((cbk ^ bM7[p]) & 7u) << 4); \
                LDMX4(b[2*p][0], b[2*p][1], b[2*p+1][0], b[2*p+1][1], addr);   \
            }                                                                  \
            _Pragma("unroll")                                                  \
            for (int mf = 0; mf < 2; mf++)                                     \
                _Pragma("unroll")                                              \
                for (int nf = 0; nf < 8; nf++)                                 \
                    asm volatile(                                              \
                        "mma.sync.aligned.m16n8k16.row.col.f32.bf16.bf16.f32 " \
                        "{%0,%1,%2,%3},{%4,%5,%6,%7},{%8,%9},{%0,%1,%2,%3};"   \
                        : "+f"(acc[mf][nf][0]), "+f"(acc[mf][nf][1]),          \
                          "+f"(acc[mf][nf][2]), "+f"(acc[mf][nf][3])           \
                        : "r"(a[mf][0]), "r"(a[mf][1]), "r"(a[mf][2]), "r"(a[mf][3]), \
                          "r"(b[nf][0]), "r"(b[nf][1]));                       \
        }                                                                      \
    }

    LOAD_CHUNK(0, 0);
    LOAD_CHUNK(1, 1);
    LOAD_CHUNK(2, 2);

    CP_WAIT(2); __syncthreads();
    MMA_CHUNK(0);
    __syncthreads();
    LOAD_CHUNK(0, 3);

    CP_WAIT(2); __syncthreads();
    MMA_CHUNK(1);

    CP_WAIT(1); __syncthreads();
    MMA_CHUNK(2);

    CP_WAIT(0); __syncthreads();
    MMA_CHUNK(0);

    // epilogue pass 1: per-row block min
#pragma unroll
    for (int mf = 0; mf < 2; mf++)
#pragma unroll
        for (int h = 0; h < 2; h++) {
            int rlo = wm * 32 + mf * 16 + g + h * 8;
            float rmin = CUDART_INF_F;
#pragma unroll
            for (int nf = 0; nf < 8; nf++) {
                int cl = wn * 64 + nf * 8 + 2 * tg;
                float s0 = s_ee[cl]     - 2.0f * acc[mf][nf][h * 2 + 0];
                float s1 = s_ee[cl + 1] - 2.0f * acc[mf][nf][h * 2 + 1];
                rmin = fminf(rmin, fminf(s0, s1));
            }
            atomicMin(&s_rmin[rlo], fmap(rmin));
        }
    __syncthreads();
    if (tid < 128) {
        unsigned mine = s_rmin[tid];
        unsigned old  = atomicMin(&g_rowmin[row0 + tid], mine);
        float gmin = fminf(funmap(old), funmap(mine));
        float sqee = sqrtf(__uint_as_float(g_maxee));
        s_thr[tid] = gmin + 0.024f * sqrtf(g_zz[row0 + tid]) * sqee + 2e-5f;
    }
    __syncthreads();
    // epilogue pass 2: append
#pragma unroll
    for (int mf = 0; mf < 2; mf++)
#pragma unroll
        for (int h = 0; h < 2; h++) {
            int rlo = wm * 32 + mf * 16 + g + h * 8;
            int grow = row0 + rlo;
            float thr = s_thr[rlo];
#pragma unroll
            for (int nf = 0; nf < 8; nf++) {
                int cl = wn * 64 + nf * 8 + 2 * tg;
                float s0 = s_ee[cl]     - 2.0f * acc[mf][nf][h * 2 + 0];
                float s1 = s_ee[cl + 1] - 2.0f * acc[mf][nf][h * 2 + 1];
                if (s0 <= thr) {
                    int p = atomicAdd(&g_ccount[grow], 1);
                    if (p < CAP) g_clist[grow][p] = cand0 + cl;
                }
                if (s1 <= thr) {
                    int p = atomicAdd(&g_ccount[grow], 1);
                    if (p < CAP) g_clist[grow][p] = cand0 + cl + 1;
                }
            }
        }
}

// ---------------------------------------------------------------------------
// FFMA screen (separate kernel => separate register allocation, no spills):
// exact fp32 scores, CTA 128 rows x 128 cands, K chunks of 16 double-buffered
// (R2 mainloop). candTiles [CT_TENSOR, 64). Scores exact -> thr = gmin +
// eps_bf16 (0.012, covers bf16-produced gmin) + tiny slack.
// ---------------------------------------------------------------------------
__global__ void __launch_bounds__(256) screen_ffma(const float* __restrict__ cb) {
    __shared__ float As[2][16][128];
    __shared__ float Bs[2][16][132];
    __shared__ unsigned s_rmin[128];
    __shared__ float s_thr[128];

    const int tid = threadIdx.x;
    const int tx = tid & 15, ty = tid >> 4;
    const int l_row = tid & 127, l_ds = tid >> 7;   // A loader: row + d-slot
    const int b_dv = tid & 3, b_k0 = tid >> 2;      // B loader

    const int rowTile = blockIdx.x & 127;
    const int cand0 = (FF_CT0 + (blockIdx.x >> 7)) * 128;
    const int row0 = rowTile * 128;
    const float* Abase = g_Azf + (size_t)row0 * EDIM;
    const float* Bbase = cb + (size_t)cand0 * EDIM;
    const float sqee = sqrtf(__uint_as_float(g_maxee));

    if (tid < 128) s_rmin[tid] = 0xFFFFFFFFu;

    float acc[8][8];
#pragma unroll
    for (int i = 0; i < 8; i++)
#pragma unroll
        for (int j = 0; j < 8; j++) acc[i][j] = 0.0f;

    float4 rA[2], rB[2];
    // prologue: chunk 0 -> buffer 0
#pragma unroll
    for (int it = 0; it < 2; it++) {
        int d4 = l_ds + it * 2;
        rA[it] = *(const float4*)(Abase + (size_t)l_row * EDIM + d4 * 4);
        int k = b_k0 + it * 64;
        rB[it] = *(const float4*)(Bbase + (size_t)k * EDIM + b_dv * 4);
    }
#pragma unroll
    for (int it = 0; it < 2; it++) {
        int d4 = l_ds + it * 2;
        As[0][d4 * 4 + 0][l_row] = rA[it].x;
        As[0][d4 * 4 + 1][l_row] = rA[it].y;
        As[0][d4 * 4 + 2][l_row] = rA[it].z;
        As[0][d4 * 4 + 3][l_row] = rA[it].w;
        int k = b_k0 + it * 64;
        Bs[0][b_dv * 4 + 0][k] = rB[it].x;
        Bs[0][b_dv * 4 + 1][k] = rB[it].y;
        Bs[0][b_dv * 4 + 2][k] = rB[it].z;
        Bs[0][b_dv * 4 + 3][k] = rB[it].w;
    }
    __syncthreads();

    int cur = 0;
#pragma unroll 1
    for (int dc = 0; dc < 16; dc++) {
        const bool has_next = (dc + 1 < 16);
        if (has_next) {
            int dbase = (dc + 1) * 16;
#pragma unroll
            for (int it = 0; it < 2; it++) {
                int d4 = l_ds + it * 2;
                rA[it] = *(const float4*)(Abase + (size_t)l_row * EDIM + dbase + d4 * 4);
                int k = b_k0 + it * 64;
                rB[it] = *(const float4*)(Bbase + (size_t)k * EDIM + dbase + b_dv * 4);
            }
        }
#pragma unroll
        for (int d = 0; d < 16; d++) {
            float a[8], bv[8];
            *(float4*)(&a[0])  = *(const float4*)(&As[cur][d][ty * 8]);
            *(float4*)(&a[4])  = *(const float4*)(&As[cur][d][ty * 8 + 4]);
            *(float4*)(&bv[0]) = *(const float4*)(&Bs[cur][d][tx * 4]);
            *(float4*)(&bv[4]) = *(const float4*)(&Bs[cur][d][64 + tx * 4]);
#pragma unroll
            for (int i = 0; i < 8; i++)
#pragma unroll
                for (int j = 0; j < 8; j++)
                    acc[i][j] = fmaf(a[i], bv[j], acc[i][j]);
        }
        if (has_next) {
            int nxt = cur ^ 1;
#pragma unroll
            for (int it = 0; it < 2; it++) {
                int d4 = l_ds + it * 2;
                As[nxt][d4 * 4 + 0][l_row] = rA[it].x;
                As[nxt][d4 * 4 + 1][l_row] = rA[it].y;
                As[nxt][d4 * 4 + 2][l_row] = rA[it].z;
                As[nxt][d4 * 4 + 3][l_row] = rA[it].w;
                int k = b_k0 + it * 64;
                Bs[nxt][b_dv * 4 + 0][k] = rB[it].x;
                Bs[nxt][b_dv * 4 + 1][k] = rB[it].y;
                Bs[nxt][b_dv * 4 + 2][k] = rB[it].z;
                Bs[nxt][b_dv * 4 + 3][k] = rB[it].w;
            }
            __syncthreads();
            cur = nxt;
        }
    }

    // scores: cand j<4 -> tx*4+j ; j>=4 -> 64+tx*4+(j-4)
    float eek[8];
#pragma unroll
    for (int j = 0; j < 8; j++) {
        int cl = (j < 4) ? (tx * 4 + j) : (64 + tx * 4 + j - 4);
        eek[j] = __ldg(&g_ee[cand0 + cl]);
    }
    // pass 1: per-row min
#pragma unroll
    for (int i = 0; i < 8; i++) {
        float rmin = CUDART_INF_F;
#pragma unroll
        for (int j = 0; j < 8; j++)
            rmin = fminf(rmin, eek[j] - 2.0f * acc[i][j]);
        atomicMin(&s_rmin[ty * 8 + i], fmap(rmin));
    }
    __syncthreads();
    if (tid < 128) {
        unsigned mine = s_rmin[tid];
        unsigned old  = atomicMin(&g_rowmin[row0 + tid], mine);
        float gmin = fminf(funmap(old), funmap(mine));
        s_thr[tid] = gmin + 0.012f * sqrtf(g_zz[row0 + tid]) * sqee + 1e-5f;
    }
    __syncthreads();
    // pass 2: append
#pragma unroll
    for (int i = 0; i < 8; i++) {
        int grow = row0 + ty * 8 + i;
        float thr = s_thr[ty * 8 + i];
#pragma unroll
        for (int j = 0; j < 8; j++) {
            float s = eek[j] - 2.0f * acc[i][j];
            if (s <= thr) {
                int cl = (j < 4) ? (tx * 4 + j) : (64 + tx * 4 + j - 4);
                int p = atomicAdd(&g_ccount[grow], 1);
                if (p < CAP) g_clist[grow][p] = cand0 + cl;
            }
        }
    }
}

// ---------------------------------------------------------------------------
// rescore: exact fp32 (ascending-d fmaf chain) + reference rounding,
// lexicographic (d, idx) min -> first-index ties. Warp per row.
// ---------------------------------------------------------------------------
__global__ void rescore_kernel(const float* __restrict__ cb) {
    int w = (blockIdx.x * blockDim.x + threadIdx.x) >> 5;
    int lane = threadIdx.x & 31;
    if (w >= NROWS) return;
    int cnt = g_ccount[w];
    float zzv = g_zz[w];
    const float* zr = g_Azf + (size_t)w * EDIM;
    float bd = CUDART_INF_F;
    int bi = 0x7FFFFFFF;
    if (cnt <= CAP) {
        for (int sl = lane; sl < cnt; sl += 32) {
            int k = g_clist[w][sl];
            const float* er = cb + (size_t)k * EDIM;
            float s = 0.0f;
#pragma unroll 8
            for (int d = 0; d < EDIM; d++) s = fmaf(zr[d], er[d], s);
            float t = __fadd_rn(zzv, g_ee[k]);
            float dv = __fadd_rn(t, -2.0f * s);
            if (dv < bd || (dv == bd && k < bi)) { bd = dv; bi = k; }
        }
    } else {  // overflow (rare): exact scan of all candidates
        for (int k = lane; k < NE; k += 32) {
            const float* er = cb + (size_t)k * EDIM;
            float s = 0.0f;
#pragma unroll 8
            for (int d = 0; d < EDIM; d++) s = fmaf(zr[d], er[d], s);
            float t = __fadd_rn(zzv, g_ee[k]);
            float dv = __fadd_rn(t, -2.0f * s);
            if (dv < bd || (dv == bd && k < bi)) { bd = dv; bi = k; }
        }
    }
#pragma unroll
    for (int o = 16; o; o >>= 1) {
        float od = __shfl_xor_sync(0xFFFFFFFFu, bd, o);
        int   oi = __shfl_xor_sync(0xFFFFFFFFu, bi, o);
        if (od < bd || (od == bd && oi < bi)) { bd = od; bi = oi; }
    }
    if (lane == 0) g_idx[w] = bi;
}

// ---------------------------------------------------------------------------
// output: z_q gather + loss, float4 over hw
// ---------------------------------------------------------------------------
__global__ void output_kernel(const float* __restrict__ z,
                              const float* __restrict__ cb,
                              float* __restrict__ out) {
    float lsum = 0.0f;
    int stride = gridDim.x * blockDim.x;
    for (int o4 = blockIdx.x * blockDim.x + threadIdx.x; o4 < ZQ_ELEMS / 4; o4 += stride) {
        int o   = o4 * 4;
        int bq  = o >> 18;
        int c   = (o >> 10) & 255;
        int hw  = o & 1023;
        int n0  = (bq << 10) | hw;
        float4 zp = *(const float4*)(z + o);
        float4 q;
        q.x = __ldg(&cb[(size_t)g_idx[n0 + 0] * EDIM + c]);
        q.y = __ldg(&cb[(size_t)g_idx[n0 + 1] * EDIM + c]);
        q.z = __ldg(&cb[(size_t)g_idx[n0 + 2] * EDIM + c]);
        q.w = __ldg(&cb[(size_t)g_idx[n0 + 3] * EDIM + c]);
        *(float4*)(out + o) = q;
        float dx = q.x - zp.x, dy = q.y - zp.y, dz = q.z - zp.z, dw = q.w - zp.w;
        lsum += dx * dx + dy * dy + dz * dz + dw * dw;
    }
    __shared__ float red[256];
    red[threadIdx.x] = lsum;
    __syncthreads();
    for (int s = 128; s > 0; s >>= 1) {
        if (threadIdx.x < s) red[threadIdx.x] += red[threadIdx.x + s];
        __syncthreads();
    }
    if (threadIdx.x == 0) atomicAdd(&g_loss, (double)red[0]);
}

__global__ void finalize_kernel(float* __restrict__ out, int out_size) {
    int t = blockIdx.x * blockDim.x + threadIdx.x;
    if (t == 0 && out_size > LOSS_OFF) {
        float m = (float)(g_loss * (1.0 / 4194304.0));
        out[LOSS_OFF] = __fadd_rn(m, 0.25f * m);
    }
    if (t < NROWS && out_size >= IDX_OFF + NROWS) {
        out[IDX_OFF + t] = (float)g_idx[t];
    }
}

// ---------------------------------------------------------------------------
extern "C" void kernel_launch(void* const* d_in, const int* in_sizes, int n_in,
                              void* d_out, int out_size) {
    const float* z  = (const float*)d_in[0];
    const float* cb = (const float*)d_in[1];
    float* out = (float*)d_out;

    cudaFuncSetAttribute(screen_kernel,
                         cudaFuncAttributeMaxDynamicSharedMemorySize, SCREEN_SMEM);

    init_kernel<<<1, 1>>>();
    prep_kernel<<<(NROWS + NE + 255) / 256, 256>>>(z, cb);
    split_cb_kernel<<<(NE * EDIM) / 256, 256>>>(cb);
    split_z_kernel<<<dim3(HWSZ / 32, CH / 32, 16), dim3(32, 8)>>>(z);

    // fork: FFMA screen on stream 2, tensor screen on default stream
    cudaEventRecord(g_ev1, 0);
    cudaStreamWaitEvent(g_s2, g_ev1, 0);
    screen_ffma<<<128 * CT_FFMA, 256, 0, g_s2>>>(cb);
    cudaEventRecord(g_ev2, g_s2);
    screen_kernel<<<128 * CT_TENSOR, 256, SCREEN_SMEM>>>();
    cudaStreamWaitEvent(0, g_ev2, 0);   // join before rescore

    rescore_kernel<<<(NROWS * 32) / 256, 256>>>(cb);
    output_kernel<<<1024, 256>>>(z, cb, out);
    finalize_kernel<<<(NROWS + 255) / 256, 256>>>(out, out_size);
}

// round 15
// speedup vs baseline: 1.5164x; 1.5164x over previous
#include <cuda_runtime.h>
#include <cuda_fp16.h>
#include <cuda_bf16.h>
#include <math_constants.h>
#include <cstdint>

// ---------------------------------------------------------------- constants
#define NROWS 16384   // B*H*W
#define NE    8192
#define EDIM  256
#define CH    256
#define HWSZ  1024
#define ZQ_ELEMS 4194304
#define LOSS_OFF 4194304
#define IDX_OFF  4194305
#define CAP   64      // shortlist capacity per row

#define SCREEN_SMEM 99840

// ---------------------------------------------------------------- scratch
__device__ float    g_zz[NROWS];
__device__ float    g_ee[NE];
__device__ int      g_idx[NROWS];
__device__ double   g_loss;
__device__ unsigned g_done;
__device__ unsigned g_maxee;
__device__ unsigned g_rowmin[NROWS];        // order-mapped float
__device__ int      g_ccount[NROWS];
__device__ int      g_clist[NROWS][CAP];
__device__ float    g_Azf[NROWS * EDIM];    // z transposed, fp32
__device__ uint16_t g_Abf[NROWS * EDIM];    // z transposed, bf16
__device__ uint16_t g_Bbf[NE * EDIM];       // codebook, bf16

// ---- second stream + fork/join events, created pre-main (no device mem)
static cudaStream_t g_s2;
static cudaEvent_t  g_ev1, g_ev2;
namespace {
struct StreamInit {
    StreamInit() {
        cudaStreamCreateWithFlags(&g_s2, cudaStreamNonBlocking);
        cudaEventCreateWithFlags(&g_ev1, cudaEventDisableTiming);
        cudaEventCreateWithFlags(&g_ev2, cudaEventDisableTiming);
    }
};
StreamInit g_stream_init;
}

__device__ __forceinline__ unsigned fmap(float f) {
    unsigned u = __float_as_uint(f);
    return (u & 0x80000000u) ? ~u : (u | 0x80000000u);
}
__device__ __forceinline__ float funmap(unsigned u) {
    u = (u & 0x80000000u) ? (u & 0x7FFFFFFFu) : ~u;
    return __uint_as_float(u);
}
__device__ __forceinline__ uint32_t smem_u32(const void* p) {
    uint32_t a;
    asm("{ .reg .u64 t; cvta.to.shared.u64 t, %1; cvt.u32.u64 %0, t; }" : "=r"(a) : "l"(p));
    return a;
}

// ---------------------------------------------------------------------------
__global__ void init_kernel() { g_maxee = 0; g_loss = 0.0; g_done = 0; }

// prep_z: zz per row (ref rounding: unfused mul+add, ascending c; NCHW reads
// are coalesced across lanes) + reset rowmin/ccount
__global__ void prep_z_kernel(const float* __restrict__ z) {
    int t = blockIdx.x * blockDim.x + threadIdx.x;
    if (t < NROWS) {
        g_rowmin[t] = 0xFFFFFFFFu;
        g_ccount[t] = 0;
        int b = t >> 10, hw = t & 1023;
        const float* p = z + (size_t)b * CH * HWSZ + hw;
        float s = 0.0f;
#pragma unroll 8
        for (int c = 0; c < CH; c++) {
            float v = p[c * HWSZ];
            s = __fadd_rn(s, __fmul_rn(v, v));
        }
        g_zz[t] = s;
    }
}

// ee: coalesced smem-tiled version; identical ascending-d rounding chain.
// block (32,8) handles 32 cb rows; 8 d-tiles of 32.
__global__ void ee_kernel(const float* __restrict__ cb) {
    __shared__ float s[32][33];
    const int row0 = blockIdx.x * 32;
    const int tx = threadIdx.x, ty = threadIdx.y;
    float acc = 0.0f;   // meaningful only for ty == 0 (row owner = tx)
#pragma unroll 1
    for (int i = 0; i < 8; i++) {
        __syncthreads();
#pragma unroll
        for (int j = 0; j < 4; j++) {
            int r = ty + j * 8;
            s[r][tx] = cb[(size_t)(row0 + r) * EDIM + i * 32 + tx];
        }
        __syncthreads();
        if (ty == 0) {
#pragma unroll
            for (int d = 0; d < 32; d++) {
                float v = s[tx][d];
                acc = __fadd_rn(acc, __fmul_rn(v, v));
            }
        }
    }
    if (ty == 0) {
        g_ee[row0 + tx] = acc;
        atomicMax(&g_maxee, __float_as_uint(acc));   // acc >= 0: uint order ok
    }
}

// codebook -> bf16
__global__ void split_cb_kernel(const float* __restrict__ cb) {
    int i = blockIdx.x * blockDim.x + threadIdx.x;
    if (i < NE * EDIM) {
        __nv_bfloat16 h = __float2bfloat16_rn(cb[i]);
        g_Bbf[i] = *(uint16_t*)&h;
    }
}

// z: NCHW -> row-major [NROWS][EDIM], fp32 + bf16
__global__ void split_z_kernel(const float* __restrict__ z) {
    __shared__ float s[32][33];
    int b = blockIdx.z, c0 = blockIdx.y * 32, hw0 = blockIdx.x * 32;
    int tx = threadIdx.x, ty = threadIdx.y;   // block (32, 8)
    const float* zp = z + ((size_t)b * CH + c0) * HWSZ + hw0;
#pragma unroll
    for (int i = 0; i < 4; i++) {
        int cl = ty + i * 8;
        s[cl][tx] = zp[(size_t)cl * HWSZ + tx];
    }
    __syncthreads();
#pragma unroll
    for (int i = 0; i < 4; i++) {
        int hl = ty + i * 8;
        size_t o = (size_t)(b * HWSZ + hw0 + hl) * EDIM + c0 + tx;
        float x = s[tx][hl];
        g_Azf[o] = x;
        __nv_bfloat16 h = __float2bfloat16_rn(x);
        g_Abf[o] = *(uint16_t*)&h;
    }
}

// ---------------------------------------------------------------------------
// screening GEMM (R7, proven): bf16 mma.sync + ldmatrix + cp.async 3-stage
// pipeline. CTA 128 rows x 128 cands, K=256 in 4 chunks of 64.
// Epilogue: per-row block min -> global running atomicMin -> append cands
// within (running_min + margin).
// ---------------------------------------------------------------------------
extern __shared__ __align__(16) uint8_t dsmem[];

#define CP_ASYNC(dst, src) \
    asm volatile("cp.async.cg.shared.global [%0], [%1], 16;" :: "r"(dst), "l"(src) : "memory")
#define CP_COMMIT() asm volatile("cp.async.commit_group;" ::: "memory")
#define CP_WAIT(n)  asm volatile("cp.async.wait_group %0;" :: "n"(n) : "memory")
#define LDMX4(r0, r1, r2, r3, addr)                                            \
    asm volatile("ldmatrix.sync.aligned.m8n8.x4.shared.b16 {%0,%1,%2,%3}, [%4];" \
                 : "=r"(r0), "=r"(r1), "=r"(r2), "=r"(r3) : "r"(addr))

__global__ void __launch_bounds__(256, 2) screen_kernel() {
    const int tid = threadIdx.x, lane = tid & 31, wid = tid >> 5;
    const int rowTile  = blockIdx.x & 127;   // fast-varying: first wave covers all rows
    const int candTile = blockIdx.x >> 7;
    const int row0 = rowTile * 128, cand0 = candTile * 128;
    const int wm = wid & 3, wn = wid >> 2;
    const int g = lane >> 2, tg = lane & 3;

    uint8_t*  sAp    = dsmem;                      // 3 stages x 16KB
    uint8_t*  sBp    = dsmem + 49152;              // 3 stages x 16KB
    unsigned* s_rmin = (unsigned*)(dsmem + 98304);
    float*    s_thr  = (float*)(dsmem + 98816);
    float*    s_ee   = (float*)(dsmem + 99328);
    const uint32_t smA = smem_u32(sAp);
    const uint32_t smB = smem_u32(sBp);

    if (tid < 128) {
        s_rmin[tid] = 0xFFFFFFFFu;
        s_ee[tid]   = g_ee[cand0 + tid];
    }

    const int rl  = lane & 7;
    const int sel = lane >> 3;
    uint32_t aOff[2], aM7[2];
#pragma unroll
    for (int mf = 0; mf < 2; mf++) {
        int row = wm * 32 + mf * 16 + (sel & 1) * 8 + rl;
        aOff[mf] = (uint32_t)(row * 128);
        aM7[mf]  = (uint32_t)(row & 7);
    }
    const uint32_t aCs = (uint32_t)(sel >> 1);
    uint32_t bOff[4], bM7[4];
#pragma unroll
    for (int p = 0; p < 4; p++) {
        int row = wn * 64 + p * 16 + (sel >> 1) * 8 + rl;
        bOff[p] = (uint32_t)(row * 128);
        bM7[p]  = (uint32_t)(row & 7);
    }
    const uint32_t bCs = (uint32_t)(sel & 1);

    float acc[2][8][4];
#pragma unroll
    for (int mf = 0; mf < 2; mf++)
#pragma unroll
        for (int nf = 0; nf < 8; nf++)
#pragma unroll
            for (int q = 0; q < 4; q++) acc[mf][nf][q] = 0.0f;

#define LOAD_CHUNK(stage, kc)                                                  \
    {                                                                          \
        _Pragma("unroll")                                                      \
        for (int it = 0; it < 4; it++) {                                       \
            int u = tid + it * 256;                                            \
            int r = u >> 3, c = u & 7;                                         \
            uint32_t so = (uint32_t)((stage) * 16384 + r * 128 + ((c ^ (r & 7)) << 4)); \
            CP_ASYNC(smA + so, g_Abf + (size_t)(row0 + r) * EDIM + (kc) * 64 + c * 8);  \
            CP_ASYNC(smB + so, g_Bbf + (size_t)(cand0 + r) * EDIM + (kc) * 64 + c * 8); \
        }                                                                      \
        CP_COMMIT();                                                           \
    }
#define MMA_CHUNK(stage)                                                       \
    {                                                                          \
        const uint32_t bufA = smA + (stage) * 16384;                           \
        const uint32_t bufB = smB + (stage) * 16384;                           \
        _Pragma("unroll")                                                      \
        for (int ks = 0; ks < 4; ks++) {                                       \
            uint32_t a[2][4], b[8][2];                                         \
            const uint32_t ca  = (uint32_t)(2 * ks) + aCs;                     \
            const uint32_t cbk = (uint32_t)(2 * ks) + bCs;                     \
            _Pragma("unroll")                                                  \
            for (int mf = 0; mf < 2; mf++) {                                   \
                uint32_t addr = bufA + aOff[mf] + (((ca ^ aM7[mf]) & 7u) << 4); \
                LDMX4(a[mf][0], a[mf][1], a[mf][2], a[mf][3], addr);           \
            }                                                                  \
            _Pragma("unroll")                                                  \
            for (int p = 0; p < 4; p++) {                                      \
                uint32_t addr = bufB + bOff[p] + (((cbk ^ bM7[p]) & 7u) << 4); \
                LDMX4(b[2*p][0], b[2*p][1], b[2*p+1][0], b[2*p+1][1], addr);   \
            }                                                                  \
            _Pragma("unroll")                                                  \
            for (int mf = 0; mf < 2; mf++)                                     \
                _Pragma("unroll")                                              \
                for (int nf = 0; nf < 8; nf++)                                 \
                    asm volatile(                                              \
                        "mma.sync.aligned.m16n8k16.row.col.f32.bf16.bf16.f32 " \
                        "{%0,%1,%2,%3},{%4,%5,%6,%7},{%8,%9},{%0,%1,%2,%3};"   \
                        : "+f"(acc[mf][nf][0]), "+f"(acc[mf][nf][1]),          \
                          "+f"(acc[mf][nf][2]), "+f"(acc[mf][nf][3])           \
                        : "r"(a[mf][0]), "r"(a[mf][1]), "r"(a[mf][2]), "r"(a[mf][3]), \
                          "r"(b[nf][0]), "r"(b[nf][1]));                       \
        }                                                                      \
    }

    LOAD_CHUNK(0, 0);
    LOAD_CHUNK(1, 1);
    LOAD_CHUNK(2, 2);

    CP_WAIT(2); __syncthreads();      // chunk 0 ready
    MMA_CHUNK(0);
    __syncthreads();                  // stage 0 free
    LOAD_CHUNK(0, 3);

    CP_WAIT(2); __syncthreads();      // chunk 1 ready
    MMA_CHUNK(1);

    CP_WAIT(1); __syncthreads();      // chunk 2 ready
    MMA_CHUNK(2);

    CP_WAIT(0); __syncthreads();      // chunk 3 ready (in stage 0)
    MMA_CHUNK(0);

    // ---- epilogue pass 1: per-row block min
#pragma unroll
    for (int mf = 0; mf < 2; mf++)
#pragma unroll
        for (int h = 0; h < 2; h++) {
            int rlo = wm * 32 + mf * 16 + g + h * 8;
            float rmin = CUDART_INF_F;
#pragma unroll
            for (int nf = 0; nf < 8; nf++) {
                int cl = wn * 64 + nf * 8 + 2 * tg;
                float s0 = s_ee[cl]     - 2.0f * acc[mf][nf][h * 2 + 0];
                float s1 = s_ee[cl + 1] - 2.0f * acc[mf][nf][h * 2 + 1];
                rmin = fminf(rmin, fminf(s0, s1));
            }
            atomicMin(&s_rmin[rlo], fmap(rmin));
        }
    __syncthreads();
    if (tid < 128) {
        unsigned mine = s_rmin[tid];
        unsigned old  = atomicMin(&g_rowmin[row0 + tid], mine);
        float gmin = fminf(funmap(old), funmap(mine));
        float sqee = sqrtf(__uint_as_float(g_maxee));
        s_thr[tid] = gmin + 0.024f * sqrtf(g_zz[row0 + tid]) * sqee + 2e-5f;
    }
    __syncthreads();
    // ---- epilogue pass 2: append candidates under threshold
#pragma unroll
    for (int mf = 0; mf < 2; mf++)
#pragma unroll
        for (int h = 0; h < 2; h++) {
            int rlo = wm * 32 + mf * 16 + g + h * 8;
            int grow = row0 + rlo;
            float thr = s_thr[rlo];
#pragma unroll
            for (int nf = 0; nf < 8; nf++) {
                int cl = wn * 64 + nf * 8 + 2 * tg;
                float s0 = s_ee[cl]     - 2.0f * acc[mf][nf][h * 2 + 0];
                float s1 = s_ee[cl + 1] - 2.0f * acc[mf][nf][h * 2 + 1];
                if (s0 <= thr) {
                    int p = atomicAdd(&g_ccount[grow], 1);
                    if (p < CAP) g_clist[grow][p] = cand0 + cl;
                }
                if (s1 <= thr) {
                    int p = atomicAdd(&g_ccount[grow], 1);
                    if (p < CAP) g_clist[grow][p] = cand0 + cl + 1;
                }
            }
        }
}

// ---------------------------------------------------------------------------
// rescore: exact fp32 (ascending-d fmaf chain) + reference rounding,
// lexicographic (d, idx) min -> first-index ties. Warp per row.
// Also writes the idx floats into out (replaces finalize's idx pass).
// ---------------------------------------------------------------------------
__global__ void rescore_kernel(const float* __restrict__ cb,
                               float* __restrict__ out, int out_size) {
    int w = (blockIdx.x * blockDim.x + threadIdx.x) >> 5;
    int lane = threadIdx.x & 31;
    if (w >= NROWS) return;
    int cnt = g_ccount[w];
    float zzv = g_zz[w];
    const float* zr = g_Azf + (size_t)w * EDIM;
    float bd = CUDART_INF_F;
    int bi = 0x7FFFFFFF;
    if (cnt <= CAP) {
        for (int sl = lane; sl < cnt; sl += 32) {
            int k = g_clist[w][sl];
            const float* er = cb + (size_t)k * EDIM;
            float s = 0.0f;
#pragma unroll 8
            for (int d = 0; d < EDIM; d++) s = fmaf(zr[d], er[d], s);
            float t = __fadd_rn(zzv, g_ee[k]);
            float dv = __fadd_rn(t, -2.0f * s);
            if (dv < bd || (dv == bd && k < bi)) { bd = dv; bi = k; }
        }
    } else {  // overflow (rare): exact scan of all candidates
        for (int k = lane; k < NE; k += 32) {
            const float* er = cb + (size_t)k * EDIM;
            float s = 0.0f;
#pragma unroll 8
            for (int d = 0; d < EDIM; d++) s = fmaf(zr[d], er[d], s);
            float t = __fadd_rn(zzv, g_ee[k]);
            float dv = __fadd_rn(t, -2.0f * s);
            if (dv < bd || (dv == bd && k < bi)) { bd = dv; bi = k; }
        }
    }
#pragma unroll
    for (int o = 16; o; o >>= 1) {
        float od = __shfl_xor_sync(0xFFFFFFFFu, bd, o);
        int   oi = __shfl_xor_sync(0xFFFFFFFFu, bi, o);
        if (od < bd || (od == bd && oi < bi)) { bd = od; bi = oi; }
    }
    if (lane == 0) {
        g_idx[w] = bi;
        if (out_size >= IDX_OFF + NROWS) out[IDX_OFF + w] = (float)bi;
    }
}

// ---------------------------------------------------------------------------
// output: z_q gather + loss (float4 over hw); last block writes loss scalar
// ---------------------------------------------------------------------------
__global__ void output_kernel(const float* __restrict__ z,
                              const float* __restrict__ cb,
                              float* __restrict__ out, int out_size) {
    float lsum = 0.0f;
    int stride = gridDim.x * blockDim.x;
    for (int o4 = blockIdx.x * blockDim.x + threadIdx.x; o4 < ZQ_ELEMS / 4; o4 += stride) {
        int o   = o4 * 4;
        int bq  = o >> 18;
        int c   = (o >> 10) & 255;
        int hw  = o & 1023;
        int n0  = (bq << 10) | hw;
        float4 zp = *(const float4*)(z + o);
        float4 q;
        q.x = __ldg(&cb[(size_t)g_idx[n0 + 0] * EDIM + c]);
        q.y = __ldg(&cb[(size_t)g_idx[n0 + 1] * EDIM + c]);
        q.z = __ldg(&cb[(size_t)g_idx[n0 + 2] * EDIM + c]);
        q.w = __ldg(&cb[(size_t)g_idx[n0 + 3] * EDIM + c]);
        *(float4*)(out + o) = q;
        float dx = q.x - zp.x, dy = q.y - zp.y, dz = q.z - zp.z, dw = q.w - zp.w;
        lsum += dx * dx + dy * dy + dz * dz + dw * dw;
    }
    __shared__ float red[256];
    red[threadIdx.x] = lsum;
    __syncthreads();
    for (int s = 128; s > 0; s >>= 1) {
        if (threadIdx.x < s) red[threadIdx.x] += red[threadIdx.x + s];
        __syncthreads();
    }
    if (threadIdx.x == 0) {
        atomicAdd(&g_loss, (double)red[0]);
        __threadfence();
        unsigned done = atomicAdd(&g_done, 1u);
        if (done == gridDim.x - 1) {
            double L = atomicAdd(&g_loss, 0.0);   // fresh read after fence chain
            float m = (float)(L * (1.0 / 4194304.0));
            if (out_size > LOSS_OFF) out[LOSS_OFF] = __fadd_rn(m, 0.25f * m);
        }
    }
}

// ---------------------------------------------------------------------------
extern "C" void kernel_launch(void* const* d_in, const int* in_sizes, int n_in,
                              void* d_out, int out_size) {
    const float* z  = (const float*)d_in[0];
    const float* cb = (const float*)d_in[1];
    float* out = (float*)d_out;

    cudaFuncSetAttribute(screen_kernel,
                         cudaFuncAttributeMaxDynamicSharedMemorySize, SCREEN_SMEM);

    init_kernel<<<1, 1>>>();

    // fork: cb-side chain on stream 2, z-side chain on default stream
    cudaEventRecord(g_ev1, 0);
    cudaStreamWaitEvent(g_s2, g_ev1, 0);
    split_cb_kernel<<<(NE * EDIM) / 256, 256, 0, g_s2>>>(cb);
    ee_kernel<<<NE / 32, dim3(32, 8), 0, g_s2>>>(cb);
    cudaEventRecord(g_ev2, g_s2);

    prep_z_kernel<<<NROWS / 256, 256>>>(z);
    split_z_kernel<<<dim3(HWSZ / 32, CH / 32, 16), dim3(32, 8)>>>(z);
    cudaStreamWaitEvent(0, g_ev2, 0);   // join before screen

    screen_kernel<<<128 * 64, 256, SCREEN_SMEM>>>();
    rescore_kernel<<<(NROWS * 32) / 256, 256>>>(cb, out, out_size);
    output_kernel<<<1024, 256>>>(z, cb, out, out_size);
}

// round 16
// speedup vs baseline: 1.5434x; 1.0178x over previous
#include <cuda_runtime.h>
#include <cuda_fp16.h>
#include <cuda_bf16.h>
#include <math_constants.h>
#include <cstdint>

// ---------------------------------------------------------------- constants
#define NROWS 16384   // B*H*W
#define NE    8192
#define EDIM  256
#define CH    256
#define HWSZ  1024
#define ZQ_ELEMS 4194304
#define LOSS_OFF 4194304
#define IDX_OFF  4194305
#define CAP   64      // shortlist capacity per row

#define SCREEN_SMEM 99840

// ---------------------------------------------------------------- scratch
__device__ float    g_zz[NROWS];
__device__ float    g_ee[NE];
__device__ int      g_idx[NROWS];
__device__ double   g_loss;
__device__ unsigned g_done;
__device__ unsigned g_maxee;
__device__ unsigned g_rowmin[NROWS];        // order-mapped float
__device__ int      g_ccount[NROWS];
__device__ int      g_clist[NROWS][CAP];
__device__ float    g_Azf[NROWS * EDIM];    // z transposed, fp32
__device__ uint16_t g_Abf[NROWS * EDIM];    // z transposed, bf16
__device__ uint16_t g_Bbf[NE * EDIM];       // codebook, bf16

// ---- extra streams + fork/join events, created pre-main (no device mem)
static cudaStream_t g_s2, g_s3;
static cudaEvent_t  g_ev1, g_ev2, g_ev3;
namespace {
struct StreamInit {
    StreamInit() {
        cudaStreamCreateWithFlags(&g_s2, cudaStreamNonBlocking);
        cudaStreamCreateWithFlags(&g_s3, cudaStreamNonBlocking);
        cudaEventCreateWithFlags(&g_ev1, cudaEventDisableTiming);
        cudaEventCreateWithFlags(&g_ev2, cudaEventDisableTiming);
        cudaEventCreateWithFlags(&g_ev3, cudaEventDisableTiming);
    }
};
StreamInit g_stream_init;
}

__device__ __forceinline__ unsigned fmap(float f) {
    unsigned u = __float_as_uint(f);
    return (u & 0x80000000u) ? ~u : (u | 0x80000000u);
}
__device__ __forceinline__ float funmap(unsigned u) {
    u = (u & 0x80000000u) ? (u & 0x7FFFFFFFu) : ~u;
    return __uint_as_float(u);
}
__device__ __forceinline__ uint32_t smem_u32(const void* p) {
    uint32_t a;
    asm("{ .reg .u64 t; cvta.to.shared.u64 t, %1; cvt.u32.u64 %0, t; }" : "=r"(a) : "l"(p));
    return a;
}

// ---------------------------------------------------------------------------
__global__ void init_kernel() { g_maxee = 0; g_loss = 0.0; g_done = 0; }

// prep_z: zz per row. Rounding chain is strictly sequential ascending-c
// (unfused mul+add) — only load batching is widened (unroll 32 -> MLP ~32).
__global__ void prep_z_kernel(const float* __restrict__ z) {
    int t = blockIdx.x * blockDim.x + threadIdx.x;
    if (t < NROWS) {
        g_rowmin[t] = 0xFFFFFFFFu;
        g_ccount[t] = 0;
        int b = t >> 10, hw = t & 1023;
        const float* p = z + (size_t)b * CH * HWSZ + hw;
        float s = 0.0f;
#pragma unroll 32
        for (int c = 0; c < CH; c++) {
            float v = __ldg(&p[c * HWSZ]);
            s = __fadd_rn(s, __fmul_rn(v, v));
        }
        g_zz[t] = s;
    }
}

// ee: coalesced smem-tiled; identical ascending-d rounding chain.
__global__ void ee_kernel(const float* __restrict__ cb) {
    __shared__ float s[32][33];
    const int row0 = blockIdx.x * 32;
    const int tx = threadIdx.x, ty = threadIdx.y;
    float acc = 0.0f;   // meaningful only for ty == 0 (row owner = tx)
#pragma unroll 1
    for (int i = 0; i < 8; i++) {
        __syncthreads();
#pragma unroll
        for (int j = 0; j < 4; j++) {
            int r = ty + j * 8;
            s[r][tx] = cb[(size_t)(row0 + r) * EDIM + i * 32 + tx];
        }
        __syncthreads();
        if (ty == 0) {
#pragma unroll
            for (int d = 0; d < 32; d++) {
                float v = s[tx][d];
                acc = __fadd_rn(acc, __fmul_rn(v, v));
            }
        }
    }
    if (ty == 0) {
        g_ee[row0 + tx] = acc;
        atomicMax(&g_maxee, __float_as_uint(acc));   // acc >= 0: uint order ok
    }
}

// codebook -> bf16
__global__ void split_cb_kernel(const float* __restrict__ cb) {
    int i = blockIdx.x * blockDim.x + threadIdx.x;
    if (i < NE * EDIM) {
        __nv_bfloat16 h = __float2bfloat16_rn(cb[i]);
        g_Bbf[i] = *(uint16_t*)&h;
    }
}

// z: NCHW -> row-major [NROWS][EDIM], fp32 + bf16
__global__ void split_z_kernel(const float* __restrict__ z) {
    __shared__ float s[32][33];
    int b = blockIdx.z, c0 = blockIdx.y * 32, hw0 = blockIdx.x * 32;
    int tx = threadIdx.x, ty = threadIdx.y;   // block (32, 8)
    const float* zp = z + ((size_t)b * CH + c0) * HWSZ + hw0;
#pragma unroll
    for (int i = 0; i < 4; i++) {
        int cl = ty + i * 8;
        s[cl][tx] = zp[(size_t)cl * HWSZ + tx];
    }
    __syncthreads();
#pragma unroll
    for (int i = 0; i < 4; i++) {
        int hl = ty + i * 8;
        size_t o = (size_t)(b * HWSZ + hw0 + hl) * EDIM + c0 + tx;
        float x = s[tx][hl];
        g_Azf[o] = x;
        __nv_bfloat16 h = __float2bfloat16_rn(x);
        g_Abf[o] = *(uint16_t*)&h;
    }
}

// ---------------------------------------------------------------------------
// screening GEMM (R7, proven): bf16 mma.sync + ldmatrix + cp.async 3-stage
// pipeline. CTA 128 rows x 128 cands, K=256 in 4 chunks of 64.
// Epilogue: per-row block min -> global running atomicMin -> append cands
// within (running_min + margin).
// ---------------------------------------------------------------------------
extern __shared__ __align__(16) uint8_t dsmem[];

#define CP_ASYNC(dst, src) \
    asm volatile("cp.async.cg.shared.global [%0], [%1], 16;" :: "r"(dst), "l"(src) : "memory")
#define CP_COMMIT() asm volatile("cp.async.commit_group;" ::: "memory")
#define CP_WAIT(n)  asm volatile("cp.async.wait_group %0;" :: "n"(n) : "memory")
#define LDMX4(r0, r1, r2, r3, addr)                                            \
    asm volatile("ldmatrix.sync.aligned.m8n8.x4.shared.b16 {%0,%1,%2,%3}, [%4];" \
                 : "=r"(r0), "=r"(r1), "=r"(r2), "=r"(r3) : "r"(addr))

__global__ void __launch_bounds__(256, 2) screen_kernel() {
    const int tid = threadIdx.x, lane = tid & 31, wid = tid >> 5;
    const int rowTile  = blockIdx.x & 127;   // fast-varying: first wave covers all rows
    const int candTile = blockIdx.x >> 7;
    const int row0 = rowTile * 128, cand0 = candTile * 128;
    const int wm = wid & 3, wn = wid >> 2;
    const int g = lane >> 2, tg = lane & 3;

    uint8_t*  sAp    = dsmem;                      // 3 stages x 16KB
    uint8_t*  sBp    = dsmem + 49152;              // 3 stages x 16KB
    unsigned* s_rmin = (unsigned*)(dsmem + 98304);
    float*    s_thr  = (float*)(dsmem + 98816);
    float*    s_ee   = (float*)(dsmem + 99328);
    const uint32_t smA = smem_u32(sAp);
    const uint32_t smB = smem_u32(sBp);

    if (tid < 128) {
        s_rmin[tid] = 0xFFFFFFFFu;
        s_ee[tid]   = g_ee[cand0 + tid];
    }

    const int rl  = lane & 7;
    const int sel = lane >> 3;
    uint32_t aOff[2], aM7[2];
#pragma unroll
    for (int mf = 0; mf < 2; mf++) {
        int row = wm * 32 + mf * 16 + (sel & 1) * 8 + rl;
        aOff[mf] = (uint32_t)(row * 128);
        aM7[mf]  = (uint32_t)(row & 7);
    }
    const uint32_t aCs = (uint32_t)(sel >> 1);
    uint32_t bOff[4], bM7[4];
#pragma unroll
    for (int p = 0; p < 4; p++) {
        int row = wn * 64 + p * 16 + (sel >> 1) * 8 + rl;
        bOff[p] = (uint32_t)(row * 128);
        bM7[p]  = (uint32_t)(row & 7);
    }
    const uint32_t bCs = (uint32_t)(sel & 1);

    float acc[2][8][4];
#pragma unroll
    for (int mf = 0; mf < 2; mf++)
#pragma unroll
        for (int nf = 0; nf < 8; nf++)
#pragma unroll
            for (int q = 0; q < 4; q++) acc[mf][nf][q] = 0.0f;

#define LOAD_CHUNK(stage, kc)                                                  \
    {                                                                          \
        _Pragma("unroll")                                                      \
        for (int it = 0; it < 4; it++) {                                       \
            int u = tid + it * 256;                                            \
            int r = u >> 3, c = u & 7;                                         \
            uint32_t so = (uint32_t)((stage) * 16384 + r * 128 + ((c ^ (r & 7)) << 4)); \
            CP_ASYNC(smA + so, g_Abf + (size_t)(row0 + r) * EDIM + (kc) * 64 + c * 8);  \
            CP_ASYNC(smB + so, g_Bbf + (size_t)(cand0 + r) * EDIM + (kc) * 64 + c * 8); \
        }                                                                      \
        CP_COMMIT();                                                           \
    }
#define MMA_CHUNK(stage)                                                       \
    {                                                                          \
        const uint32_t bufA = smA + (stage) * 16384;                           \
        const uint32_t bufB = smB + (stage) * 16384;                           \
        _Pragma("unroll")                                                      \
        for (int ks = 0; ks < 4; ks++) {                                       \
            uint32_t a[2][4], b[8][2];                                         \
            const uint32_t ca  = (uint32_t)(2 * ks) + aCs;                     \
            const uint32_t cbk = (uint32_t)(2 * ks) + bCs;                     \
            _Pragma("unroll")                                                  \
            for (int mf = 0; mf < 2; mf++) {                                   \
                uint32_t addr = bufA + aOff[mf] + (((ca ^ aM7[mf]) & 7u) << 4); \
                LDMX4(a[mf][0], a[mf][1], a[mf][2], a[mf][3], addr);           \
            }                                                                  \
            _Pragma("unroll")                                                  \
            for (int p = 0; p < 4; p++) {                                      \
                uint32_t addr = bufB + bOff[p] + (((cbk ^ bM7[p]) & 7u) << 4); \
                LDMX4(b[2*p][0], b[2*p][1], b[2*p+1][0], b[2*p+1][1], addr);   \
            }                                                                  \
            _Pragma("unroll")                                                  \
            for (int mf = 0; mf < 2; mf++)                                     \
                _Pragma("unroll")                                              \
                for (int nf = 0; nf < 8; nf++)                                 \
                    asm volatile(                                              \
                        "mma.sync.aligned.m16n8k16.row.col.f32.bf16.bf16.f32 " \
                        "{%0,%1,%2,%3},{%4,%5,%6,%7},{%8,%9},{%0,%1,%2,%3};"   \
                        : "+f"(acc[mf][nf][0]), "+f"(acc[mf][nf][1]),          \
                          "+f"(acc[mf][nf][2]), "+f"(acc[mf][nf][3])           \
                        : "r"(a[mf][0]), "r"(a[mf][1]), "r"(a[mf][2]), "r"(a[mf][3]), \
                          "r"(b[nf][0]), "r"(b[nf][1]));                       \
        }                                                                      \
    }

    LOAD_CHUNK(0, 0);
    LOAD_CHUNK(1, 1);
    LOAD_CHUNK(2, 2);

    CP_WAIT(2); __syncthreads();      // chunk 0 ready
    MMA_CHUNK(0);
    __syncthreads();                  // stage 0 free
    LOAD_CHUNK(0, 3);

    CP_WAIT(2); __syncthreads();      // chunk 1 ready
    MMA_CHUNK(1);

    CP_WAIT(1); __syncthreads();      // chunk 2 ready
    MMA_CHUNK(2);

    CP_WAIT(0); __syncthreads();      // chunk 3 ready (in stage 0)
    MMA_CHUNK(0);

    // ---- epilogue pass 1: per-row block min
#pragma unroll
    for (int mf = 0; mf < 2; mf++)
#pragma unroll
        for (int h = 0; h < 2; h++) {
            int rlo = wm * 32 + mf * 16 + g + h * 8;
            float rmin = CUDART_INF_F;
#pragma unroll
            for (int nf = 0; nf < 8; nf++) {
                int cl = wn * 64 + nf * 8 + 2 * tg;
                float s0 = s_ee[cl]     - 2.0f * acc[mf][nf][h * 2 + 0];
                float s1 = s_ee[cl + 1] - 2.0f * acc[mf][nf][h * 2 + 1];
                rmin = fminf(rmin, fminf(s0, s1));
            }
            atomicMin(&s_rmin[rlo], fmap(rmin));
        }
    __syncthreads();
    if (tid < 128) {
        unsigned mine = s_rmin[tid];
        unsigned old  = atomicMin(&g_rowmin[row0 + tid], mine);
        float gmin = fminf(funmap(old), funmap(mine));
        float sqee = sqrtf(__uint_as_float(g_maxee));
        s_thr[tid] = gmin + 0.024f * sqrtf(g_zz[row0 + tid]) * sqee + 2e-5f;
    }
    __syncthreads();
    // ---- epilogue pass 2: append candidates under threshold
#pragma unroll
    for (int mf = 0; mf < 2; mf++)
#pragma unroll
        for (int h = 0; h < 2; h++) {
            int rlo = wm * 32 + mf * 16 + g + h * 8;
            int grow = row0 + rlo;
            float thr = s_thr[rlo];
#pragma unroll
            for (int nf = 0; nf < 8; nf++) {
                int cl = wn * 64 + nf * 8 + 2 * tg;
                float s0 = s_ee[cl]     - 2.0f * acc[mf][nf][h * 2 + 0];
                float s1 = s_ee[cl + 1] - 2.0f * acc[mf][nf][h * 2 + 1];
                if (s0 <= thr) {
                    int p = atomicAdd(&g_ccount[grow], 1);
                    if (p < CAP) g_clist[grow][p] = cand0 + cl;
                }
                if (s1 <= thr) {
                    int p = atomicAdd(&g_ccount[grow], 1);
                    if (p < CAP) g_clist[grow][p] = cand0 + cl + 1;
                }
            }
        }
}

// ---------------------------------------------------------------------------
// rescore: exact fp32 (ascending-d fmaf chain) + reference rounding,
// lexicographic (d, idx) min -> first-index ties. Warp per row.
// Also writes the idx floats into out.
// ---------------------------------------------------------------------------
__global__ void rescore_kernel(const float* __restrict__ cb,
                               float* __restrict__ out, int out_size) {
    int w = (blockIdx.x * blockDim.x + threadIdx.x) >> 5;
    int lane = threadIdx.x & 31;
    if (w >= NROWS) return;
    int cnt = g_ccount[w];
    float zzv = g_zz[w];
    const float* zr = g_Azf + (size_t)w * EDIM;
    float bd = CUDART_INF_F;
    int bi = 0x7FFFFFFF;
    if (cnt <= CAP) {
        for (int sl = lane; sl < cnt; sl += 32) {
            int k = g_clist[w][sl];
            const float* er = cb + (size_t)k * EDIM;
            float s = 0.0f;
#pragma unroll 8
            for (int d = 0; d < EDIM; d++) s = fmaf(zr[d], er[d], s);
            float t = __fadd_rn(zzv, g_ee[k]);
            float dv = __fadd_rn(t, -2.0f * s);
            if (dv < bd || (dv == bd && k < bi)) { bd = dv; bi = k; }
        }
    } else {  // overflow (rare): exact scan of all candidates
        for (int k = lane; k < NE; k += 32) {
            const float* er = cb + (size_t)k * EDIM;
            float s = 0.0f;
#pragma unroll 8
            for (int d = 0; d < EDIM; d++) s = fmaf(zr[d], er[d], s);
            float t = __fadd_rn(zzv, g_ee[k]);
            float dv = __fadd_rn(t, -2.0f * s);
            if (dv < bd || (dv == bd && k < bi)) { bd = dv; bi = k; }
        }
    }
#pragma unroll
    for (int o = 16; o; o >>= 1) {
        float od = __shfl_xor_sync(0xFFFFFFFFu, bd, o);
        int   oi = __shfl_xor_sync(0xFFFFFFFFu, bi, o);
        if (od < bd || (od == bd && oi < bi)) { bd = od; bi = oi; }
    }
    if (lane == 0) {
        g_idx[w] = bi;
        if (out_size >= IDX_OFF + NROWS) out[IDX_OFF + w] = (float)bi;
    }
}

// ---------------------------------------------------------------------------
// output: z_q gather + loss (float4 over hw); last block writes loss scalar
// ---------------------------------------------------------------------------
__global__ void output_kernel(const float* __restrict__ z,
                              const float* __restrict__ cb,
                              float* __restrict__ out, int out_size) {
    float lsum = 0.0f;
    int stride = gridDim.x * blockDim.x;
    for (int o4 = blockIdx.x * blockDim.x + threadIdx.x; o4 < ZQ_ELEMS / 4; o4 += stride) {
        int o   = o4 * 4;
        int bq  = o >> 18;
        int c   = (o >> 10) & 255;
        int hw  = o & 1023;
        int n0  = (bq << 10) | hw;
        float4 zp = *(const float4*)(z + o);
        float4 q;
        q.x = __ldg(&cb[(size_t)g_idx[n0 + 0] * EDIM + c]);
        q.y = __ldg(&cb[(size_t)g_idx[n0 + 1] * EDIM + c]);
        q.z = __ldg(&cb[(size_t)g_idx[n0 + 2] * EDIM + c]);
        q.w = __ldg(&cb[(size_t)g_idx[n0 + 3] * EDIM + c]);
        *(float4*)(out + o) = q;
        float dx = q.x - zp.x, dy = q.y - zp.y, dz = q.z - zp.z, dw = q.w - zp.w;
        lsum += dx * dx + dy * dy + dz * dz + dw * dw;
    }
    __shared__ float red[256];
    red[threadIdx.x] = lsum;
    __syncthreads();
    for (int s = 128; s > 0; s >>= 1) {
        if (threadIdx.x < s) red[threadIdx.x] += red[threadIdx.x + s];
        __syncthreads();
    }
    if (threadIdx.x == 0) {
        atomicAdd(&g_loss, (double)red[0]);
        __threadfence();
        unsigned done = atomicAdd(&g_done, 1u);
        if (done == gridDim.x - 1) {
            double L = atomicAdd(&g_loss, 0.0);
            float m = (float)(L * (1.0 / 4194304.0));
            if (out_size > LOSS_OFF) out[LOSS_OFF] = __fadd_rn(m, 0.25f * m);
        }
    }
}

// ---------------------------------------------------------------------------
extern "C" void kernel_launch(void* const* d_in, const int* in_sizes, int n_in,
                              void* d_out, int out_size) {
    const float* z  = (const float*)d_in[0];
    const float* cb = (const float*)d_in[1];
    float* out = (float*)d_out;

    cudaFuncSetAttribute(screen_kernel,
                         cudaFuncAttributeMaxDynamicSharedMemorySize, SCREEN_SMEM);

    init_kernel<<<1, 1>>>();

    // 3-way fork: cb chain on s2, prep_z on s3, split_z on default
    cudaEventRecord(g_ev1, 0);
    cudaStreamWaitEvent(g_s2, g_ev1, 0);
    cudaStreamWaitEvent(g_s3, g_ev1, 0);

    split_cb_kernel<<<(NE * EDIM) / 256, 256, 0, g_s2>>>(cb);
    ee_kernel<<<NE / 32, dim3(32, 8), 0, g_s2>>>(cb);
    cudaEventRecord(g_ev2, g_s2);

    prep_z_kernel<<<NROWS / 256, 256, 0, g_s3>>>(z);
    cudaEventRecord(g_ev3, g_s3);

    split_z_kernel<<<dim3(HWSZ / 32, CH / 32, 16), dim3(32, 8)>>>(z);
    cudaStreamWaitEvent(0, g_ev2, 0);   // join cb chain
    cudaStreamWaitEvent(0, g_ev3, 0);   // join prep_z

    screen_kernel<<<128 * 64, 256, SCREEN_SMEM>>>();
    rescore_kernel<<<(NROWS * 32) / 256, 256>>>(cb, out, out_size);
    output_kernel<<<1024, 256>>>(z, cb, out, out_size);
}